// round 10
// baseline (speedup 1.0000x reference)
#include <cuda_runtime.h>
#include <cstdint>

#define BB 8
#define C 256
#define G 16
#define KK 9
#define GKK 144
#define HW 4096
#define IMG_W 64
#define IMG_H 64

typedef unsigned long long u64;
typedef unsigned int u32;

__device__ __align__(16) float g_kmap[BB * GKK * HW];

// ---------- scalar helpers ----------
__device__ __forceinline__ u64 ffma2(u64 a, u64 b, u64 c) {
    u64 d; asm("fma.rn.f32x2 %0, %1, %2, %3;" : "=l"(d) : "l"(a), "l"(b), "l"(c)); return d;
}
__device__ __forceinline__ u64 pk(float lo, float hi) {
    u64 r; asm("mov.b64 %0, {%1, %2};" : "=l"(r) : "f"(lo), "f"(hi)); return r;
}
__device__ __forceinline__ float lo32(u64 v) { return __uint_as_float((u32)v); }
__device__ __forceinline__ float hi32(u64 v) { return __uint_as_float((u32)(v >> 32)); }
__device__ __forceinline__ u32 bf2(float lo, float hi) {
    u32 r; asm("cvt.rn.bf16x2.f32 %0, %1, %2;" : "=r"(r) : "f"(hi), "f"(lo)); return r;
}
__device__ __forceinline__ void split2(float v0, float v1, u32& h2, u32& l2) {
    h2 = bf2(v0, v1);
    l2 = bf2(v0 - __uint_as_float(h2 << 16), v1 - __uint_as_float(h2 & 0xFFFF0000u));
}
__device__ __forceinline__ void cvt4(float4 v, u64& h, u64& l) {
    u32 h0, l0, h1, l1;
    split2(v.x, v.y, h0, l0);
    split2(v.z, v.w, h1, l1);
    h = (u64)h0 | ((u64)h1 << 32);
    l = (u64)l0 | ((u64)l1 << 32);
}
__device__ __forceinline__ u32 smem_u32(const void* p) {
    u32 a; asm("{ .reg .u64 t; cvta.to.shared.u64 t, %1; cvt.u32.u64 %0, t; }" : "=r"(a) : "l"(p));
    return a;
}

#define MMA(d, a, b0, b1) \
    asm volatile("mma.sync.aligned.m16n8k16.row.col.f32.bf16.bf16.f32 " \
        "{%0,%1,%2,%3}, {%4,%5,%6,%7}, {%8,%9}, {%0,%1,%2,%3};" \
        : "+f"((d)[0]), "+f"((d)[1]), "+f"((d)[2]), "+f"((d)[3]) \
        : "r"((a)[0]), "r"((a)[1]), "r"((a)[2]), "r"((a)[3]), "r"(b0), "r"(b1))

#define LDSM4T(r, addr) \
    asm volatile("ldmatrix.sync.aligned.m8n8.x4.trans.shared.b16 {%0,%1,%2,%3}, [%4];" \
        : "=r"((r)[0]), "=r"((r)[1]), "=r"((r)[2]), "=r"((r)[3]) : "r"(addr))

// smem byte layout
#define OFF_XH   0        // 2 bufs x [32 k][128 px] bf16 (256B rows) = 2*8192
#define OFF_XL   16384
#define OFF_W1H  32768    // 2 bufs x [64 n][40 k] bf16 (80B rows) = 2*5120
#define OFF_W1L  43008
#define OFF_WSPH 53248    // [144 n][72 k] bf16 (144B rows) = 20736
#define OFF_WSPL 73984
#define SM_TOTAL 94720

// ---------------------------------------------------------------------------
// k_gemm: both 1x1 convs as HMMA GEMMs, bf16 split-2 (hh+hl+lh).
// CTA = 128 px tile, 8 warps; each warp = 16 px rows x all N.
// hid stays in registers between the two GEMMs (C-frag == A-frag layout).
// ---------------------------------------------------------------------------
__global__ __launch_bounds__(256, 2)
void k_gemm(const float* __restrict__ x, const float* __restrict__ wr,
            const float* __restrict__ br, const float* __restrict__ wsp,
            const float* __restrict__ bs) {
    extern __shared__ __align__(16) char smem[];
    const int tid = threadIdx.x, wid = tid >> 5, lane = tid & 31;
    const int b = blockIdx.x >> 5, pt = (blockIdx.x & 31) << 7;
    const u32 sbase = smem_u32(smem);

    // ---- w_span -> smem bf16 hi/lo, rows padded to 72 elems (144B) ----
#pragma unroll
    for (int i = 0; i < 9; i++) {
        int f4 = tid + i * 256;                    // 2304 float4 total
        float4 v = *(const float4*)(wsp + f4 * 4);
        int n = f4 >> 4, kc = (f4 & 15) * 4;
        u64 h, l;
        cvt4(v, h, l);
        *(u64*)(smem + OFF_WSPH + n * 144 + kc * 2) = h;
        *(u64*)(smem + OFF_WSPL + n * 144 + kc * 2) = l;
    }

    // ---- prologue: chunk 0 of x and w_reduce ----
    {
        const int c = tid >> 3, pxb = (tid & 7) * 16;
        const float* xsrc = x + ((size_t)(b * C + c)) * HW + pt + pxb;
        const int csw = (c & 7) << 3;
#pragma unroll
        for (int q = 0; q < 4; q++) {
            float4 v = *(const float4*)(xsrc + q * 4);
            int col = (pxb + q * 4) ^ csw;
            u64 h, l;
            cvt4(v, h, l);
            *(u64*)(smem + OFF_XH + c * 256 + col * 2) = h;
            *(u64*)(smem + OFF_XL + c * 256 + col * 2) = l;
        }
        const int n = tid >> 2, koff = (tid & 3) * 8;
#pragma unroll
        for (int q = 0; q < 2; q++) {
            float4 v = *(const float4*)(wr + n * C + koff + q * 4);
            u64 h, l;
            cvt4(v, h, l);
            *(u64*)(smem + OFF_W1H + n * 80 + (koff + q * 4) * 2) = h;
            *(u64*)(smem + OFF_W1L + n * 80 + (koff + q * 4) * 2) = l;
        }
    }
    __syncthreads();

    float acc1[8][4];
#pragma unroll
    for (int j = 0; j < 8; j++)
#pragma unroll
        for (int q = 0; q < 4; q++) acc1[j][q] = 0.f;

    const int m0 = wid * 16;
    const int grp = lane >> 3, li = lane & 7;
    const int krow_off = ((grp & 2) << 2) + li;
    const int coladd = (grp & 1) << 3;
    const u32 bB1 = (u32)((lane >> 2) * 80 + ((lane & 3) << 2));
    const u32 bB2 = (u32)((lane >> 2) * 144 + ((lane & 3) << 2));

    // ---- stage 1: K=256 in 8 chunks of 32, double buffered ----
#pragma unroll 1
    for (int ck = 0; ck < 8; ck++) {
        const int cur = ck & 1, nxt = cur ^ 1;
        float4 xr[4], wrr[2];
        if (ck < 7) {
            const int c = tid >> 3, pxb = (tid & 7) * 16;
            const float* xsrc = x + ((size_t)(b * C + (ck + 1) * 32 + c)) * HW + pt + pxb;
#pragma unroll
            for (int q = 0; q < 4; q++) xr[q] = *(const float4*)(xsrc + q * 4);
            const int n = tid >> 2, koff = (tid & 3) * 8;
#pragma unroll
            for (int q = 0; q < 2; q++)
                wrr[q] = *(const float4*)(wr + n * C + (ck + 1) * 32 + koff + q * 4);
        }
        const u32 sxh = sbase + OFF_XH + cur * 8192;
        const char* w1h = smem + OFF_W1H + cur * 5120;
        const char* w1l = smem + OFF_W1L + cur * 5120;

#pragma unroll
        for (int ks = 0; ks < 2; ks++) {
            const int kb = ks * 16;
            u32 AH[4], AL[4];
            {
                int col = (m0 + coladd) ^ (li << 3);
                u32 ah = sxh + (u32)((kb + krow_off) * 256 + col * 2);
                LDSM4T(AH, ah);
                LDSM4T(AL, ah + 16384);   // XL plane at fixed +16384
            }
#pragma unroll
            for (int nj = 0; nj < 8; nj++) {
                u32 off = bB1 + nj * 640 + kb * 2;
                u32 bh0 = *(const u32*)(w1h + off);
                u32 bh1 = *(const u32*)(w1h + off + 16);
                u32 bl0 = *(const u32*)(w1l + off);
                u32 bl1 = *(const u32*)(w1l + off + 16);
                MMA(acc1[nj], AH, bh0, bh1);
                MMA(acc1[nj], AH, bl0, bl1);
                MMA(acc1[nj], AL, bh0, bh1);
            }
        }
        if (ck < 7) {
            const int c = tid >> 3, pxb = (tid & 7) * 16;
            const int csw = (c & 7) << 3;
#pragma unroll
            for (int q = 0; q < 4; q++) {
                int col = (pxb + q * 4) ^ csw;
                u64 h, l;
                cvt4(xr[q], h, l);
                *(u64*)(smem + OFF_XH + nxt * 8192 + c * 256 + col * 2) = h;
                *(u64*)(smem + OFF_XL + nxt * 8192 + c * 256 + col * 2) = l;
            }
            const int n = tid >> 2, koff = (tid & 3) * 8;
#pragma unroll
            for (int q = 0; q < 2; q++) {
                u64 h, l;
                cvt4(wrr[q], h, l);
                *(u64*)(smem + OFF_W1H + nxt * 5120 + n * 80 + (koff + q * 4) * 2) = h;
                *(u64*)(smem + OFF_W1L + nxt * 5120 + n * 80 + (koff + q * 4) * 2) = l;
            }
        }
        __syncthreads();
    }

    // ---- in-register: bias+relu+split -> stage-2 A fragments ----
    u32 A2H[4][4], A2L[4][4];
#pragma unroll
    for (int ks = 0; ks < 4; ks++) {
        int o0 = ks * 16 + (lane & 3) * 2;
        float b0 = __ldg(br + o0),     b1 = __ldg(br + o0 + 1);
        float b8 = __ldg(br + o0 + 8), b9 = __ldg(br + o0 + 9);
        const float* t0 = acc1[2 * ks];
        const float* t1 = acc1[2 * ks + 1];
        float v0 = fmaxf(t0[0] + b0, 0.f), v1 = fmaxf(t0[1] + b1, 0.f);
        float v2 = fmaxf(t0[2] + b0, 0.f), v3 = fmaxf(t0[3] + b1, 0.f);
        float w0 = fmaxf(t1[0] + b8, 0.f), w1 = fmaxf(t1[1] + b9, 0.f);
        float w2 = fmaxf(t1[2] + b8, 0.f), w3 = fmaxf(t1[3] + b9, 0.f);
        split2(v0, v1, A2H[ks][0], A2L[ks][0]);
        split2(v2, v3, A2H[ks][1], A2L[ks][1]);
        split2(w0, w1, A2H[ks][2], A2L[ks][2]);
        split2(w2, w3, A2H[ks][3], A2L[ks][3]);
    }

    // ---- stage 2: N=144 (18 n-tiles), K=64 (4 k-steps) ----
    const char* wsph = smem + OFF_WSPH;
    const char* wspl = smem + OFF_WSPL;
    const int pxl = wid * 16 + (lane >> 2);
    float* kout = g_kmap + (size_t)(b * GKK) * HW + pt;
#pragma unroll 2
    for (int nj = 0; nj < 18; nj++) {
        float a2[4] = {0.f, 0.f, 0.f, 0.f};
#pragma unroll
        for (int ks = 0; ks < 4; ks++) {
            u32 off = bB2 + nj * 1152 + ks * 32;
            u32 bh0 = *(const u32*)(wsph + off);
            u32 bh1 = *(const u32*)(wsph + off + 16);
            u32 bl0 = *(const u32*)(wspl + off);
            u32 bl1 = *(const u32*)(wspl + off + 16);
            MMA(a2, A2H[ks], bh0, bh1);
            MMA(a2, A2H[ks], bl0, bl1);
            MMA(a2, A2L[ks], bh0, bh1);
        }
        int o0 = nj * 8 + (lane & 3) * 2;
        float c0 = __ldg(bs + o0), c1 = __ldg(bs + o0 + 1);
        kout[(size_t)o0 * HW + pxl]           = a2[0] + c0;
        kout[(size_t)(o0 + 1) * HW + pxl]     = a2[1] + c1;
        kout[(size_t)o0 * HW + pxl + 8]       = a2[2] + c0;
        kout[(size_t)(o0 + 1) * HW + pxl + 8] = a2[3] + c1;
    }
}

// ---------------------------------------------------------------------------
// k_invol: R6 structure + launch_bounds(256,4) to lift occupancy.
// ---------------------------------------------------------------------------
__global__ __launch_bounds__(256, 4) void k_invol(const float* __restrict__ x,
                                                  float* __restrict__ out) {
    __shared__ __align__(16) float sm[8 * 10 * 68 * 2];
    const int tid = threadIdx.x, strip = blockIdx.x, g = blockIdx.y, b = blockIdx.z;
    const int chbase = g * 16;
    const int cph = tid >> 7, rr = (tid >> 4) & 7, t4 = tid & 15;
    const int R0 = strip * 8 + rr, X0 = t4 * 4;

    const float* kbase = g_kmap + ((size_t)(b * G + g)) * KK * HW + R0 * IMG_W + X0;
    float4 km[9];
#pragma unroll
    for (int k = 0; k < 9; k++) km[k] = *(const float4*)(kbase + (size_t)k * HW);

    if (tid < 160) {
        int cp = tid / 20, rem = tid % 20;
        int r = rem >> 1, col = (rem & 1) ? 65 : 0;
        *(u64*)&sm[((cp * 10 + r) * 68 + col) * 2] = 0ull;
    }
#pragma unroll
    for (int it = 0; it < 5; it++) {
        int lin = tid + it * 256;
        int cp = lin / 160, rem = lin - cp * 160;
        int r = rem >> 4, c4 = rem & 15;
        int R = strip * 8 + r - 1;
        float4 a = make_float4(0.f, 0.f, 0.f, 0.f), c = a;
        if ((unsigned)R < (unsigned)IMG_H) {
            const float* p0 = x + ((size_t)(b * C + chbase + cp * 2)) * HW + R * IMG_W + c4 * 4;
            a = *(const float4*)p0;
            c = *(const float4*)(p0 + HW);
        }
        float* d = &sm[((cp * 10 + r) * 68 + 1 + c4 * 4) * 2];
        ((float2*)d)[0] = make_float2(a.x, c.x);
        ((float2*)d)[1] = make_float2(a.y, c.y);
        ((float2*)d)[2] = make_float2(a.z, c.z);
        ((float2*)d)[3] = make_float2(a.w, c.w);
    }
    __syncthreads();

#pragma unroll
    for (int half = 0; half < 2; half++) {
        u64 acc[2][4];
#pragma unroll
        for (int cp = 0; cp < 2; cp++)
#pragma unroll
            for (int j = 0; j < 4; j++) acc[cp][j] = 0ull;
#pragma unroll
        for (int dy = 0; dy < 3; dy++) {
            u64 km2[3][4];
#pragma unroll
            for (int dx = 0; dx < 3; dx++) {
                float4 kv = km[dy * 3 + dx];
                km2[dx][0] = pk(kv.x, kv.x); km2[dx][1] = pk(kv.y, kv.y);
                km2[dx][2] = pk(kv.z, kv.z); km2[dx][3] = pk(kv.w, kv.w);
            }
#pragma unroll
            for (int cp = 0; cp < 2; cp++) {
                const int cpi = cph * 4 + half * 2 + cp;
                const float* srow = &sm[((cpi * 10 + rr + dy) * 68 + t4 * 4) * 2];
                ulonglong2 q0 = *(const ulonglong2*)(srow);
                ulonglong2 q1 = *(const ulonglong2*)(srow + 4);
                ulonglong2 q2 = *(const ulonglong2*)(srow + 8);
                u64 p0 = q0.x, p1 = q0.y, p2 = q1.x, p3 = q1.y, p4 = q2.x, p5 = q2.y;
                acc[cp][0] = ffma2(p0, km2[0][0], acc[cp][0]);
                acc[cp][0] = ffma2(p1, km2[1][0], acc[cp][0]);
                acc[cp][0] = ffma2(p2, km2[2][0], acc[cp][0]);
                acc[cp][1] = ffma2(p1, km2[0][1], acc[cp][1]);
                acc[cp][1] = ffma2(p2, km2[1][1], acc[cp][1]);
                acc[cp][1] = ffma2(p3, km2[2][1], acc[cp][1]);
                acc[cp][2] = ffma2(p2, km2[0][2], acc[cp][2]);
                acc[cp][2] = ffma2(p3, km2[1][2], acc[cp][2]);
                acc[cp][2] = ffma2(p4, km2[2][2], acc[cp][2]);
                acc[cp][3] = ffma2(p3, km2[0][3], acc[cp][3]);
                acc[cp][3] = ffma2(p4, km2[1][3], acc[cp][3]);
                acc[cp][3] = ffma2(p5, km2[2][3], acc[cp][3]);
            }
        }
#pragma unroll
        for (int cp = 0; cp < 2; cp++) {
            const int ch = chbase + (cph * 4 + half * 2 + cp) * 2;
            float4 ev, od;
            ev.x = lo32(acc[cp][0]); od.x = hi32(acc[cp][0]);
            ev.y = lo32(acc[cp][1]); od.y = hi32(acc[cp][1]);
            ev.z = lo32(acc[cp][2]); od.z = hi32(acc[cp][2]);
            ev.w = lo32(acc[cp][3]); od.w = hi32(acc[cp][3]);
            float* ob = out + ((size_t)(b * C + ch)) * HW + R0 * IMG_W + X0;
            *(float4*)ob = ev;
            *(float4*)(ob + HW) = od;
        }
    }
}

// ---------------------------------------------------------------------------
extern "C" void kernel_launch(void* const* d_in, const int* in_sizes, int n_in,
                              void* d_out, int out_size) {
    const float* x   = (const float*)d_in[0];
    const float* wr  = (const float*)d_in[1];
    const float* br  = (const float*)d_in[2];
    const float* wsp = (const float*)d_in[3];
    const float* bs  = (const float*)d_in[4];
    float* out = (float*)d_out;

    static int once = 0;
    if (!once) {
        cudaFuncSetAttribute(k_gemm, cudaFuncAttributeMaxDynamicSharedMemorySize, SM_TOTAL);
        once = 1;
    }
    k_gemm<<<BB * (HW / 128), 256, SM_TOTAL>>>(x, wr, br, wsp, bs);
    dim3 g3(8, G, BB);
    k_invol<<<g3, 256>>>(x, out);
}

// round 11
// speedup vs baseline: 1.0464x; 1.0464x over previous
#include <cuda_runtime.h>
#include <cstdint>

#define BB 8
#define C 256
#define G 16
#define KK 9
#define GKK 144
#define HW 4096
#define IMG_W 64
#define IMG_H 64

typedef unsigned long long u64;
typedef unsigned int u32;

__device__ __align__(16) float g_kmap[BB * GKK * HW];

// ---------- scalar helpers ----------
__device__ __forceinline__ u64 ffma2(u64 a, u64 b, u64 c) {
    u64 d; asm("fma.rn.f32x2 %0, %1, %2, %3;" : "=l"(d) : "l"(a), "l"(b), "l"(c)); return d;
}
__device__ __forceinline__ u64 pk(float lo, float hi) {
    u64 r; asm("mov.b64 %0, {%1, %2};" : "=l"(r) : "f"(lo), "f"(hi)); return r;
}
__device__ __forceinline__ float lo32(u64 v) { return __uint_as_float((u32)v); }
__device__ __forceinline__ float hi32(u64 v) { return __uint_as_float((u32)(v >> 32)); }
__device__ __forceinline__ u32 bf2(float lo, float hi) {
    u32 r; asm("cvt.rn.bf16x2.f32 %0, %1, %2;" : "=r"(r) : "f"(hi), "f"(lo)); return r;
}
__device__ __forceinline__ void split2(float v0, float v1, u32& h2, u32& l2) {
    h2 = bf2(v0, v1);
    l2 = bf2(v0 - __uint_as_float(h2 << 16), v1 - __uint_as_float(h2 & 0xFFFF0000u));
}
__device__ __forceinline__ void cvt4(float4 v, u64& h, u64& l) {
    u32 h0, l0, h1, l1;
    split2(v.x, v.y, h0, l0);
    split2(v.z, v.w, h1, l1);
    h = (u64)h0 | ((u64)h1 << 32);
    l = (u64)l0 | ((u64)l1 << 32);
}
__device__ __forceinline__ u32 smem_u32(const void* p) {
    u32 a; asm("{ .reg .u64 t; cvta.to.shared.u64 t, %1; cvt.u32.u64 %0, t; }" : "=r"(a) : "l"(p));
    return a;
}

#define MMA(d, a, b0, b1) \
    asm volatile("mma.sync.aligned.m16n8k16.row.col.f32.bf16.bf16.f32 " \
        "{%0,%1,%2,%3}, {%4,%5,%6,%7}, {%8,%9}, {%0,%1,%2,%3};" \
        : "+f"((d)[0]), "+f"((d)[1]), "+f"((d)[2]), "+f"((d)[3]) \
        : "r"((a)[0]), "r"((a)[1]), "r"((a)[2]), "r"((a)[3]), "r"(b0), "r"(b1))

#define LDSM4T(r, addr) \
    asm volatile("ldmatrix.sync.aligned.m8n8.x4.trans.shared.b16 {%0,%1,%2,%3}, [%4];" \
        : "=r"((r)[0]), "=r"((r)[1]), "=r"((r)[2]), "=r"((r)[3]) : "r"(addr))

#define LDSM4(r, addr) \
    asm volatile("ldmatrix.sync.aligned.m8n8.x4.shared.b16 {%0,%1,%2,%3}, [%4];" \
        : "=r"((r)[0]), "=r"((r)[1]), "=r"((r)[2]), "=r"((r)[3]) : "r"(addr))

// smem byte layout
#define OFF_XH   0        // 2 bufs x [32 k][128 px] bf16 (256B rows) = 2*8192
#define OFF_XL   16384
#define OFF_W1H  32768    // 2 bufs x [64 n][40 k] bf16 (80B rows) = 2*5120
#define OFF_W1L  43008
#define OFF_WSPH 53248    // [144 n][72 k] bf16 (144B rows) = 20736
#define OFF_WSPL 73984
#define SM_TOTAL 94720

__global__ void noop_a() {}
__global__ void noop_b() {}

// ---------------------------------------------------------------------------
// k_gemm: both 1x1 convs as HMMA GEMMs, bf16 split-2 (hh+hl+lh).
// CTA = 128 px tile, 8 warps; warp = 16 px rows x all N.
// B fragments via ldmatrix.x4 (2 n-tiles per instr) instead of scalar LDS.
// ---------------------------------------------------------------------------
__global__ __launch_bounds__(256, 2)
void k_gemm(const float* __restrict__ x, const float* __restrict__ wr,
            const float* __restrict__ br, const float* __restrict__ wsp,
            const float* __restrict__ bs) {
    extern __shared__ __align__(16) char smem[];
    const int tid = threadIdx.x, wid = tid >> 5, lane = tid & 31;
    const int b = blockIdx.x >> 5, pt = (blockIdx.x & 31) << 7;
    const u32 sbase = smem_u32(smem);

    // ---- w_span -> smem bf16 hi/lo, rows padded to 72 elems (144B) ----
#pragma unroll
    for (int i = 0; i < 9; i++) {
        int f4 = tid + i * 256;                    // 2304 float4 total
        float4 v = *(const float4*)(wsp + f4 * 4);
        int n = f4 >> 4, kc = (f4 & 15) * 4;
        u64 h, l;
        cvt4(v, h, l);
        *(u64*)(smem + OFF_WSPH + n * 144 + kc * 2) = h;
        *(u64*)(smem + OFF_WSPL + n * 144 + kc * 2) = l;
    }

    // ---- prologue: chunk 0 of x and w_reduce ----
    {
        const int c = tid >> 3, pxb = (tid & 7) * 16;
        const float* xsrc = x + ((size_t)(b * C + c)) * HW + pt + pxb;
        const int csw = (c & 7) << 3;
#pragma unroll
        for (int q = 0; q < 4; q++) {
            float4 v = *(const float4*)(xsrc + q * 4);
            int col = (pxb + q * 4) ^ csw;
            u64 h, l;
            cvt4(v, h, l);
            *(u64*)(smem + OFF_XH + c * 256 + col * 2) = h;
            *(u64*)(smem + OFF_XL + c * 256 + col * 2) = l;
        }
        const int n = tid >> 2, koff = (tid & 3) * 8;
#pragma unroll
        for (int q = 0; q < 2; q++) {
            float4 v = *(const float4*)(wr + n * C + koff + q * 4);
            u64 h, l;
            cvt4(v, h, l);
            *(u64*)(smem + OFF_W1H + n * 80 + (koff + q * 4) * 2) = h;
            *(u64*)(smem + OFF_W1L + n * 80 + (koff + q * 4) * 2) = l;
        }
    }
    __syncthreads();

    float acc1[8][4];
#pragma unroll
    for (int j = 0; j < 8; j++)
#pragma unroll
        for (int q = 0; q < 4; q++) acc1[j][q] = 0.f;

    const int m0 = wid * 16;
    const int grp = lane >> 3, li = lane & 7;
    const int krow_off = ((grp & 2) << 2) + li;
    const int coladd = (grp & 1) << 3;
    // ldmatrix B lane mapping: matrix m=lane>>3; n-row = (m>>1)*8 + li, k add = (m&1)*8
    const int brow = ((lane >> 4) << 3) + li;      // (m>>1)*8 + li
    const int bkadd = (grp & 1) << 3;              // (m&1)*8

    // ---- stage 1: K=256 in 8 chunks of 32, double buffered ----
#pragma unroll 1
    for (int ck = 0; ck < 8; ck++) {
        const int cur = ck & 1, nxt = cur ^ 1;
        float4 xr[4], wrr[2];
        if (ck < 7) {
            const int c = tid >> 3, pxb = (tid & 7) * 16;
            const float* xsrc = x + ((size_t)(b * C + (ck + 1) * 32 + c)) * HW + pt + pxb;
#pragma unroll
            for (int q = 0; q < 4; q++) xr[q] = *(const float4*)(xsrc + q * 4);
            const int n = tid >> 2, koff = (tid & 3) * 8;
#pragma unroll
            for (int q = 0; q < 2; q++)
                wrr[q] = *(const float4*)(wr + n * C + (ck + 1) * 32 + koff + q * 4);
        }
        const u32 sxh = sbase + OFF_XH + cur * 8192;
        const u32 sw1h = sbase + OFF_W1H + cur * 5120;
        const u32 sw1l = sbase + OFF_W1L + cur * 5120;

#pragma unroll
        for (int ks = 0; ks < 2; ks++) {
            const int kb = ks * 16;
            u32 AH[4], AL[4];
            {
                int col = (m0 + coladd) ^ (li << 3);
                u32 ah = sxh + (u32)((kb + krow_off) * 256 + col * 2);
                LDSM4T(AH, ah);
                LDSM4T(AL, ah + 16384);   // XL plane at fixed +16384
            }
#pragma unroll
            for (int nj2 = 0; nj2 < 4; nj2++) {
                u32 boff = (u32)((nj2 * 16 + brow) * 80 + (kb + bkadd) * 2);
                u32 BH[4], BL[4];
                LDSM4(BH, sw1h + boff);
                LDSM4(BL, sw1l + boff);
                MMA(acc1[2 * nj2], AH, BH[0], BH[1]);
                MMA(acc1[2 * nj2], AH, BL[0], BL[1]);
                MMA(acc1[2 * nj2], AL, BH[0], BH[1]);
                MMA(acc1[2 * nj2 + 1], AH, BH[2], BH[3]);
                MMA(acc1[2 * nj2 + 1], AH, BL[2], BL[3]);
                MMA(acc1[2 * nj2 + 1], AL, BH[2], BH[3]);
            }
        }
        if (ck < 7) {
            const int c = tid >> 3, pxb = (tid & 7) * 16;
            const int csw = (c & 7) << 3;
#pragma unroll
            for (int q = 0; q < 4; q++) {
                int col = (pxb + q * 4) ^ csw;
                u64 h, l;
                cvt4(xr[q], h, l);
                *(u64*)(smem + OFF_XH + nxt * 8192 + c * 256 + col * 2) = h;
                *(u64*)(smem + OFF_XL + nxt * 8192 + c * 256 + col * 2) = l;
            }
            const int n = tid >> 2, koff = (tid & 3) * 8;
#pragma unroll
            for (int q = 0; q < 2; q++) {
                u64 h, l;
                cvt4(wrr[q], h, l);
                *(u64*)(smem + OFF_W1H + nxt * 5120 + n * 80 + (koff + q * 4) * 2) = h;
                *(u64*)(smem + OFF_W1L + nxt * 5120 + n * 80 + (koff + q * 4) * 2) = l;
            }
        }
        __syncthreads();
    }

    // ---- in-register: bias+relu+split -> stage-2 A fragments ----
    u32 A2H[4][4], A2L[4][4];
#pragma unroll
    for (int ks = 0; ks < 4; ks++) {
        int o0 = ks * 16 + (lane & 3) * 2;
        float b0 = __ldg(br + o0),     float_b1 = __ldg(br + o0 + 1);
        float b8 = __ldg(br + o0 + 8), b9 = __ldg(br + o0 + 9);
        const float* t0 = acc1[2 * ks];
        const float* t1 = acc1[2 * ks + 1];
        float v0 = fmaxf(t0[0] + b0, 0.f), v1 = fmaxf(t0[1] + float_b1, 0.f);
        float v2 = fmaxf(t0[2] + b0, 0.f), v3 = fmaxf(t0[3] + float_b1, 0.f);
        float w0 = fmaxf(t1[0] + b8, 0.f), w1 = fmaxf(t1[1] + b9, 0.f);
        float w2 = fmaxf(t1[2] + b8, 0.f), w3 = fmaxf(t1[3] + b9, 0.f);
        split2(v0, v1, A2H[ks][0], A2L[ks][0]);
        split2(v2, v3, A2H[ks][1], A2L[ks][1]);
        split2(w0, w1, A2H[ks][2], A2L[ks][2]);
        split2(w2, w3, A2H[ks][3], A2L[ks][3]);
    }

    // ---- stage 2: N=144 (9 nj-pairs), K=64 (4 k-steps), ldmatrix B ----
    const u32 swsph = sbase + OFF_WSPH;
    const u32 swspl = sbase + OFF_WSPL;
    const int pxl = wid * 16 + (lane >> 2);
    float* kout = g_kmap + (size_t)(b * GKK) * HW + pt;
#pragma unroll 1
    for (int nj2 = 0; nj2 < 9; nj2++) {
        float a2e[4] = {0.f, 0.f, 0.f, 0.f};
        float a2o[4] = {0.f, 0.f, 0.f, 0.f};
#pragma unroll
        for (int ks = 0; ks < 4; ks++) {
            u32 boff = (u32)((nj2 * 16 + brow) * 144 + (ks * 16 + bkadd) * 2);
            u32 BH[4], BL[4];
            LDSM4(BH, swsph + boff);
            LDSM4(BL, swspl + boff);
            MMA(a2e, A2H[ks], BH[0], BH[1]);
            MMA(a2e, A2H[ks], BL[0], BL[1]);
            MMA(a2e, A2L[ks], BH[0], BH[1]);
            MMA(a2o, A2H[ks], BH[2], BH[3]);
            MMA(a2o, A2H[ks], BL[2], BL[3]);
            MMA(a2o, A2L[ks], BH[2], BH[3]);
        }
#pragma unroll
        for (int half = 0; half < 2; half++) {
            const float* a2 = half ? a2o : a2e;
            int o0 = (nj2 * 2 + half) * 8 + (lane & 3) * 2;
            float c0 = __ldg(bs + o0), c1 = __ldg(bs + o0 + 1);
            kout[(size_t)o0 * HW + pxl]           = a2[0] + c0;
            kout[(size_t)(o0 + 1) * HW + pxl]     = a2[1] + c1;
            kout[(size_t)o0 * HW + pxl + 8]       = a2[2] + c0;
            kout[(size_t)(o0 + 1) * HW + pxl + 8] = a2[3] + c1;
        }
    }
}

// ---------------------------------------------------------------------------
// k_invol: unchanged from R10 (21.5us).
// ---------------------------------------------------------------------------
__global__ __launch_bounds__(256, 4) void k_invol(const float* __restrict__ x,
                                                  float* __restrict__ out) {
    __shared__ __align__(16) float sm[8 * 10 * 68 * 2];
    const int tid = threadIdx.x, strip = blockIdx.x, g = blockIdx.y, b = blockIdx.z;
    const int chbase = g * 16;
    const int cph = tid >> 7, rr = (tid >> 4) & 7, t4 = tid & 15;
    const int R0 = strip * 8 + rr, X0 = t4 * 4;

    const float* kbase = g_kmap + ((size_t)(b * G + g)) * KK * HW + R0 * IMG_W + X0;
    float4 km[9];
#pragma unroll
    for (int k = 0; k < 9; k++) km[k] = *(const float4*)(kbase + (size_t)k * HW);

    if (tid < 160) {
        int cp = tid / 20, rem = tid % 20;
        int r = rem >> 1, col = (rem & 1) ? 65 : 0;
        *(u64*)&sm[((cp * 10 + r) * 68 + col) * 2] = 0ull;
    }
#pragma unroll
    for (int it = 0; it < 5; it++) {
        int lin = tid + it * 256;
        int cp = lin / 160, rem = lin - cp * 160;
        int r = rem >> 4, c4 = rem & 15;
        int R = strip * 8 + r - 1;
        float4 a = make_float4(0.f, 0.f, 0.f, 0.f), c = a;
        if ((unsigned)R < (unsigned)IMG_H) {
            const float* p0 = x + ((size_t)(b * C + chbase + cp * 2)) * HW + R * IMG_W + c4 * 4;
            a = *(const float4*)p0;
            c = *(const float4*)(p0 + HW);
        }
        float* d = &sm[((cp * 10 + r) * 68 + 1 + c4 * 4) * 2];
        ((float2*)d)[0] = make_float2(a.x, c.x);
        ((float2*)d)[1] = make_float2(a.y, c.y);
        ((float2*)d)[2] = make_float2(a.z, c.z);
        ((float2*)d)[3] = make_float2(a.w, c.w);
    }
    __syncthreads();

#pragma unroll
    for (int half = 0; half < 2; half++) {
        u64 acc[2][4];
#pragma unroll
        for (int cp = 0; cp < 2; cp++)
#pragma unroll
            for (int j = 0; j < 4; j++) acc[cp][j] = 0ull;
#pragma unroll
        for (int dy = 0; dy < 3; dy++) {
            u64 km2[3][4];
#pragma unroll
            for (int dx = 0; dx < 3; dx++) {
                float4 kv = km[dy * 3 + dx];
                km2[dx][0] = pk(kv.x, kv.x); km2[dx][1] = pk(kv.y, kv.y);
                km2[dx][2] = pk(kv.z, kv.z); km2[dx][3] = pk(kv.w, kv.w);
            }
#pragma unroll
            for (int cp = 0; cp < 2; cp++) {
                const int cpi = cph * 4 + half * 2 + cp;
                const float* srow = &sm[((cpi * 10 + rr + dy) * 68 + t4 * 4) * 2];
                ulonglong2 q0 = *(const ulonglong2*)(srow);
                ulonglong2 q1 = *(const ulonglong2*)(srow + 4);
                ulonglong2 q2 = *(const ulonglong2*)(srow + 8);
                u64 p0 = q0.x, p1 = q0.y, p2 = q1.x, p3 = q1.y, p4 = q2.x, p5 = q2.y;
                acc[cp][0] = ffma2(p0, km2[0][0], acc[cp][0]);
                acc[cp][0] = ffma2(p1, km2[1][0], acc[cp][0]);
                acc[cp][0] = ffma2(p2, km2[2][0], acc[cp][0]);
                acc[cp][1] = ffma2(p1, km2[0][1], acc[cp][1]);
                acc[cp][1] = ffma2(p2, km2[1][1], acc[cp][1]);
                acc[cp][1] = ffma2(p3, km2[2][1], acc[cp][1]);
                acc[cp][2] = ffma2(p2, km2[0][2], acc[cp][2]);
                acc[cp][2] = ffma2(p3, km2[1][2], acc[cp][2]);
                acc[cp][2] = ffma2(p4, km2[2][2], acc[cp][2]);
                acc[cp][3] = ffma2(p3, km2[0][3], acc[cp][3]);
                acc[cp][3] = ffma2(p4, km2[1][3], acc[cp][3]);
                acc[cp][3] = ffma2(p5, km2[2][3], acc[cp][3]);
            }
        }
#pragma unroll
        for (int cp = 0; cp < 2; cp++) {
            const int ch = chbase + (cph * 4 + half * 2 + cp) * 2;
            float4 ev, od;
            ev.x = lo32(acc[cp][0]); od.x = hi32(acc[cp][0]);
            ev.y = lo32(acc[cp][1]); od.y = hi32(acc[cp][1]);
            ev.z = lo32(acc[cp][2]); od.z = hi32(acc[cp][2]);
            ev.w = lo32(acc[cp][3]); od.w = hi32(acc[cp][3]);
            float* ob = out + ((size_t)(b * C + ch)) * HW + R0 * IMG_W + X0;
            *(float4*)ob = ev;
            *(float4*)(ob + HW) = od;
        }
    }
}

// ---------------------------------------------------------------------------
extern "C" void kernel_launch(void* const* d_in, const int* in_sizes, int n_in,
                              void* d_out, int out_size) {
    const float* x   = (const float*)d_in[0];
    const float* wr  = (const float*)d_in[1];
    const float* br  = (const float*)d_in[2];
    const float* wsp = (const float*)d_in[3];
    const float* bs  = (const float*)d_in[4];
    float* out = (float*)d_out;

    static int once = 0;
    if (!once) {
        cudaFuncSetAttribute(k_gemm, cudaFuncAttributeMaxDynamicSharedMemorySize, SM_TOTAL);
        once = 1;
    }
    // 4 launches/call so ncu (-s 5) profiles k_gemm: #0-3 correctness,
    // replay1: #4 = noop_a, #5 = k_gemm.
    noop_a<<<1, 32>>>();
    k_gemm<<<BB * (HW / 128), 256, SM_TOTAL>>>(x, wr, br, wsp, bs);
    dim3 g3(8, G, BB);
    k_invol<<<g3, 256>>>(x, out);
    noop_b<<<1, 32>>>();
}

// round 12
// speedup vs baseline: 1.2018x; 1.1485x over previous
#include <cuda_runtime.h>
#include <cuda_fp16.h>
#include <cstdint>

#define BB 8
#define C 256
#define G 16
#define KK 9
#define GKK 144
#define HW 4096
#define IMG_W 64
#define IMG_H 64

typedef unsigned long long u64;
typedef unsigned int u32;

__device__ __align__(16) float g_kmap[BB * GKK * HW];

// ---------- scalar helpers ----------
__device__ __forceinline__ u64 ffma2(u64 a, u64 b, u64 c) {
    u64 d; asm("fma.rn.f32x2 %0, %1, %2, %3;" : "=l"(d) : "l"(a), "l"(b), "l"(c)); return d;
}
__device__ __forceinline__ u64 pk(float lo, float hi) {
    u64 r; asm("mov.b64 %0, {%1, %2};" : "=l"(r) : "f"(lo), "f"(hi)); return r;
}
__device__ __forceinline__ float lo32(u64 v) { return __uint_as_float((u32)v); }
__device__ __forceinline__ float hi32(u64 v) { return __uint_as_float((u32)(v >> 32)); }

// fp16 split: hi = fp16(v), lo = fp16(v - hi)
__device__ __forceinline__ u32 h2u(__half2 h) { u32 r; memcpy(&r, &h, 4); return r; }
__device__ __forceinline__ void split2h(float v0, float v1, u32& h2, u32& l2) {
    __half2 h = __floats2half2_rn(v0, v1);
    h2 = h2u(h);
    l2 = h2u(__floats2half2_rn(v0 - __low2float(h), v1 - __high2float(h)));
}
__device__ __forceinline__ void cvt4h(float4 v, u64& h, u64& l) {
    u32 h0, l0, h1, l1;
    split2h(v.x, v.y, h0, l0);
    split2h(v.z, v.w, h1, l1);
    h = (u64)h0 | ((u64)h1 << 32);
    l = (u64)l0 | ((u64)l1 << 32);
}
// fp16 single-plane convert (for weights)
__device__ __forceinline__ u64 cvt4h1(float4 v) {
    u32 a = h2u(__floats2half2_rn(v.x, v.y));
    u32 b = h2u(__floats2half2_rn(v.z, v.w));
    return (u64)a | ((u64)b << 32);
}
__device__ __forceinline__ u32 smem_u32(const void* p) {
    u32 a; asm("{ .reg .u64 t; cvta.to.shared.u64 t, %1; cvt.u32.u64 %0, t; }" : "=r"(a) : "l"(p));
    return a;
}

#define MMA(d, a, b0, b1) \
    asm volatile("mma.sync.aligned.m16n8k16.row.col.f32.f16.f16.f32 " \
        "{%0,%1,%2,%3}, {%4,%5,%6,%7}, {%8,%9}, {%0,%1,%2,%3};" \
        : "+f"((d)[0]), "+f"((d)[1]), "+f"((d)[2]), "+f"((d)[3]) \
        : "r"((a)[0]), "r"((a)[1]), "r"((a)[2]), "r"((a)[3]), "r"(b0), "r"(b1))

#define LDSM4T(r, addr) \
    asm volatile("ldmatrix.sync.aligned.m8n8.x4.trans.shared.b16 {%0,%1,%2,%3}, [%4];" \
        : "=r"((r)[0]), "=r"((r)[1]), "=r"((r)[2]), "=r"((r)[3]) : "r"(addr))

#define LDSM4(r, addr) \
    asm volatile("ldmatrix.sync.aligned.m8n8.x4.shared.b16 {%0,%1,%2,%3}, [%4];" \
        : "=r"((r)[0]), "=r"((r)[1]), "=r"((r)[2]), "=r"((r)[3]) : "r"(addr))

// smem byte layout
#define OFF_XH   0        // 2 bufs x [32 k][128 px] fp16 (256B rows) = 2*8192
#define OFF_XL   16384    // residual plane, fixed +16384 from XH
#define OFF_W1H  32768    // 2 bufs x [64 n][40 k] fp16 (80B rows) = 2*5120
#define OFF_WSPH 43008    // [144 n][72 k] fp16 (144B rows) = 20736
#define SM_TOTAL 63744

// ---------------------------------------------------------------------------
// k_gemm: both 1x1 convs as HMMA fp16 GEMMs, 2-product split (xh+xl, w 1-plane).
// CTA = 128 px tile, 8 warps; warp = 16 px rows x all N.
// hid stays in registers between the two GEMMs (C-frag == A-frag layout).
// ---------------------------------------------------------------------------
__global__ __launch_bounds__(256, 2)
void k_gemm(const float* __restrict__ x, const float* __restrict__ wr,
            const float* __restrict__ br, const float* __restrict__ wsp,
            const float* __restrict__ bs) {
    extern __shared__ __align__(16) char smem[];
    const int tid = threadIdx.x, wid = tid >> 5, lane = tid & 31;
    const int b = blockIdx.x >> 5, pt = (blockIdx.x & 31) << 7;
    const u32 sbase = smem_u32(smem);

    // ---- w_span -> smem fp16, rows padded to 72 elems (144B) ----
#pragma unroll
    for (int i = 0; i < 9; i++) {
        int f4 = tid + i * 256;                    // 2304 float4 total
        float4 v = *(const float4*)(wsp + f4 * 4);
        int n = f4 >> 4, kc = (f4 & 15) * 4;
        *(u64*)(smem + OFF_WSPH + n * 144 + kc * 2) = cvt4h1(v);
    }

    // ---- prologue: chunk 0 of x and w_reduce ----
    {
        const int c = tid >> 3, pxb = (tid & 7) * 16;
        const float* xsrc = x + ((size_t)(b * C + c)) * HW + pt + pxb;
        const int csw = (c & 7) << 3;
#pragma unroll
        for (int q = 0; q < 4; q++) {
            float4 v = *(const float4*)(xsrc + q * 4);
            int col = (pxb + q * 4) ^ csw;
            u64 h, l;
            cvt4h(v, h, l);
            *(u64*)(smem + OFF_XH + c * 256 + col * 2) = h;
            *(u64*)(smem + OFF_XL + c * 256 + col * 2) = l;
        }
        const int n = tid >> 2, koff = (tid & 3) * 8;
#pragma unroll
        for (int q = 0; q < 2; q++) {
            float4 v = *(const float4*)(wr + n * C + koff + q * 4);
            *(u64*)(smem + OFF_W1H + n * 80 + (koff + q * 4) * 2) = cvt4h1(v);
        }
    }
    __syncthreads();

    float acc1[8][4];
#pragma unroll
    for (int j = 0; j < 8; j++)
#pragma unroll
        for (int q = 0; q < 4; q++) acc1[j][q] = 0.f;

    const int m0 = wid * 16;
    const int grp = lane >> 3, li = lane & 7;
    const int krow_off = ((grp & 2) << 2) + li;
    const int coladd = (grp & 1) << 3;
    const int brow = ((lane >> 4) << 3) + li;      // ldmatrix B: n-row
    const int bkadd = (grp & 1) << 3;              // ldmatrix B: k add

    // ---- stage 1: K=256 in 8 chunks of 32, double buffered ----
#pragma unroll 1
    for (int ck = 0; ck < 8; ck++) {
        const int cur = ck & 1, nxt = cur ^ 1;
        float4 xr[4], wrr[2];
        if (ck < 7) {
            const int c = tid >> 3, pxb = (tid & 7) * 16;
            const float* xsrc = x + ((size_t)(b * C + (ck + 1) * 32 + c)) * HW + pt + pxb;
#pragma unroll
            for (int q = 0; q < 4; q++) xr[q] = *(const float4*)(xsrc + q * 4);
            const int n = tid >> 2, koff = (tid & 3) * 8;
#pragma unroll
            for (int q = 0; q < 2; q++)
                wrr[q] = *(const float4*)(wr + n * C + (ck + 1) * 32 + koff + q * 4);
        }
        const u32 sxh = sbase + OFF_XH + cur * 8192;
        const u32 sw1h = sbase + OFF_W1H + cur * 5120;

#pragma unroll
        for (int ks = 0; ks < 2; ks++) {
            const int kb = ks * 16;
            u32 AH[4], AL[4];
            {
                int col = (m0 + coladd) ^ (li << 3);
                u32 ah = sxh + (u32)((kb + krow_off) * 256 + col * 2);
                LDSM4T(AH, ah);
                LDSM4T(AL, ah + 16384);   // XL plane at fixed +16384
            }
#pragma unroll
            for (int nj2 = 0; nj2 < 4; nj2++) {
                u32 boff = (u32)((nj2 * 16 + brow) * 80 + (kb + bkadd) * 2);
                u32 BH[4];
                LDSM4(BH, sw1h + boff);
                MMA(acc1[2 * nj2], AH, BH[0], BH[1]);
                MMA(acc1[2 * nj2], AL, BH[0], BH[1]);
                MMA(acc1[2 * nj2 + 1], AH, BH[2], BH[3]);
                MMA(acc1[2 * nj2 + 1], AL, BH[2], BH[3]);
            }
        }
        if (ck < 7) {
            const int c = tid >> 3, pxb = (tid & 7) * 16;
            const int csw = (c & 7) << 3;
#pragma unroll
            for (int q = 0; q < 4; q++) {
                int col = (pxb + q * 4) ^ csw;
                u64 h, l;
                cvt4h(xr[q], h, l);
                *(u64*)(smem + OFF_XH + nxt * 8192 + c * 256 + col * 2) = h;
                *(u64*)(smem + OFF_XL + nxt * 8192 + c * 256 + col * 2) = l;
            }
            const int n = tid >> 2, koff = (tid & 3) * 8;
#pragma unroll
            for (int q = 0; q < 2; q++)
                *(u64*)(smem + OFF_W1H + nxt * 5120 + n * 80 + (koff + q * 4) * 2) = cvt4h1(wrr[q]);
        }
        __syncthreads();
    }

    // ---- in-register: bias+relu+split -> stage-2 A fragments (fp16) ----
    u32 A2H[4][4], A2L[4][4];
#pragma unroll
    for (int ks = 0; ks < 4; ks++) {
        int o0 = ks * 16 + (lane & 3) * 2;
        float b0 = __ldg(br + o0),     b1 = __ldg(br + o0 + 1);
        float b8 = __ldg(br + o0 + 8), b9 = __ldg(br + o0 + 9);
        const float* t0 = acc1[2 * ks];
        const float* t1 = acc1[2 * ks + 1];
        float v0 = fmaxf(t0[0] + b0, 0.f), v1 = fmaxf(t0[1] + b1, 0.f);
        float v2 = fmaxf(t0[2] + b0, 0.f), v3 = fmaxf(t0[3] + b1, 0.f);
        float w0 = fmaxf(t1[0] + b8, 0.f), w1 = fmaxf(t1[1] + b9, 0.f);
        float w2 = fmaxf(t1[2] + b8, 0.f), w3 = fmaxf(t1[3] + b9, 0.f);
        split2h(v0, v1, A2H[ks][0], A2L[ks][0]);
        split2h(v2, v3, A2H[ks][1], A2L[ks][1]);
        split2h(w0, w1, A2H[ks][2], A2L[ks][2]);
        split2h(w2, w3, A2H[ks][3], A2L[ks][3]);
    }

    // ---- stage 2: N=144 (9 nj-pairs), K=64 (4 k-steps), ldmatrix B ----
    const u32 swsph = sbase + OFF_WSPH;
    const int pxl = wid * 16 + (lane >> 2);
    float* kout = g_kmap + (size_t)(b * GKK) * HW + pt;
#pragma unroll 1
    for (int nj2 = 0; nj2 < 9; nj2++) {
        float a2e[4] = {0.f, 0.f, 0.f, 0.f};
        float a2o[4] = {0.f, 0.f, 0.f, 0.f};
#pragma unroll
        for (int ks = 0; ks < 4; ks++) {
            u32 boff = (u32)((nj2 * 16 + brow) * 144 + (ks * 16 + bkadd) * 2);
            u32 BH[4];
            LDSM4(BH, swsph + boff);
            MMA(a2e, A2H[ks], BH[0], BH[1]);
            MMA(a2e, A2L[ks], BH[0], BH[1]);
            MMA(a2o, A2H[ks], BH[2], BH[3]);
            MMA(a2o, A2L[ks], BH[2], BH[3]);
        }
#pragma unroll
        for (int half = 0; half < 2; half++) {
            const float* a2 = half ? a2o : a2e;
            int o0 = (nj2 * 2 + half) * 8 + (lane & 3) * 2;
            float c0 = __ldg(bs + o0), c1 = __ldg(bs + o0 + 1);
            kout[(size_t)o0 * HW + pxl]           = a2[0] + c0;
            kout[(size_t)(o0 + 1) * HW + pxl]     = a2[1] + c1;
            kout[(size_t)o0 * HW + pxl + 8]       = a2[2] + c0;
            kout[(size_t)(o0 + 1) * HW + pxl + 8] = a2[3] + c1;
        }
    }
}

// ---------------------------------------------------------------------------
// k_invol: unchanged (21.5us).
// ---------------------------------------------------------------------------
__global__ __launch_bounds__(256, 4) void k_invol(const float* __restrict__ x,
                                                  float* __restrict__ out) {
    __shared__ __align__(16) float sm[8 * 10 * 68 * 2];
    const int tid = threadIdx.x, strip = blockIdx.x, g = blockIdx.y, b = blockIdx.z;
    const int chbase = g * 16;
    const int cph = tid >> 7, rr = (tid >> 4) & 7, t4 = tid & 15;
    const int R0 = strip * 8 + rr, X0 = t4 * 4;

    const float* kbase = g_kmap + ((size_t)(b * G + g)) * KK * HW + R0 * IMG_W + X0;
    float4 km[9];
#pragma unroll
    for (int k = 0; k < 9; k++) km[k] = *(const float4*)(kbase + (size_t)k * HW);

    if (tid < 160) {
        int cp = tid / 20, rem = tid % 20;
        int r = rem >> 1, col = (rem & 1) ? 65 : 0;
        *(u64*)&sm[((cp * 10 + r) * 68 + col) * 2] = 0ull;
    }
#pragma unroll
    for (int it = 0; it < 5; it++) {
        int lin = tid + it * 256;
        int cp = lin / 160, rem = lin - cp * 160;
        int r = rem >> 4, c4 = rem & 15;
        int R = strip * 8 + r - 1;
        float4 a = make_float4(0.f, 0.f, 0.f, 0.f), c = a;
        if ((unsigned)R < (unsigned)IMG_H) {
            const float* p0 = x + ((size_t)(b * C + chbase + cp * 2)) * HW + R * IMG_W + c4 * 4;
            a = *(const float4*)p0;
            c = *(const float4*)(p0 + HW);
        }
        float* d = &sm[((cp * 10 + r) * 68 + 1 + c4 * 4) * 2];
        ((float2*)d)[0] = make_float2(a.x, c.x);
        ((float2*)d)[1] = make_float2(a.y, c.y);
        ((float2*)d)[2] = make_float2(a.z, c.z);
        ((float2*)d)[3] = make_float2(a.w, c.w);
    }
    __syncthreads();

#pragma unroll
    for (int half = 0; half < 2; half++) {
        u64 acc[2][4];
#pragma unroll
        for (int cp = 0; cp < 2; cp++)
#pragma unroll
            for (int j = 0; j < 4; j++) acc[cp][j] = 0ull;
#pragma unroll
        for (int dy = 0; dy < 3; dy++) {
            u64 km2[3][4];
#pragma unroll
            for (int dx = 0; dx < 3; dx++) {
                float4 kv = km[dy * 3 + dx];
                km2[dx][0] = pk(kv.x, kv.x); km2[dx][1] = pk(kv.y, kv.y);
                km2[dx][2] = pk(kv.z, kv.z); km2[dx][3] = pk(kv.w, kv.w);
            }
#pragma unroll
            for (int cp = 0; cp < 2; cp++) {
                const int cpi = cph * 4 + half * 2 + cp;
                const float* srow = &sm[((cpi * 10 + rr + dy) * 68 + t4 * 4) * 2];
                ulonglong2 q0 = *(const ulonglong2*)(srow);
                ulonglong2 q1 = *(const ulonglong2*)(srow + 4);
                ulonglong2 q2 = *(const ulonglong2*)(srow + 8);
                u64 p0 = q0.x, p1 = q0.y, p2 = q1.x, p3 = q1.y, p4 = q2.x, p5 = q2.y;
                acc[cp][0] = ffma2(p0, km2[0][0], acc[cp][0]);
                acc[cp][0] = ffma2(p1, km2[1][0], acc[cp][0]);
                acc[cp][0] = ffma2(p2, km2[2][0], acc[cp][0]);
                acc[cp][1] = ffma2(p1, km2[0][1], acc[cp][1]);
                acc[cp][1] = ffma2(p2, km2[1][1], acc[cp][1]);
                acc[cp][1] = ffma2(p3, km2[2][1], acc[cp][1]);
                acc[cp][2] = ffma2(p2, km2[0][2], acc[cp][2]);
                acc[cp][2] = ffma2(p3, km2[1][2], acc[cp][2]);
                acc[cp][2] = ffma2(p4, km2[2][2], acc[cp][2]);
                acc[cp][3] = ffma2(p3, km2[0][3], acc[cp][3]);
                acc[cp][3] = ffma2(p4, km2[1][3], acc[cp][3]);
                acc[cp][3] = ffma2(p5, km2[2][3], acc[cp][3]);
            }
        }
#pragma unroll
        for (int cp = 0; cp < 2; cp++) {
            const int ch = chbase + (cph * 4 + half * 2 + cp) * 2;
            float4 ev, od;
            ev.x = lo32(acc[cp][0]); od.x = hi32(acc[cp][0]);
            ev.y = lo32(acc[cp][1]); od.y = hi32(acc[cp][1]);
            ev.z = lo32(acc[cp][2]); od.z = hi32(acc[cp][2]);
            ev.w = lo32(acc[cp][3]); od.w = hi32(acc[cp][3]);
            float* ob = out + ((size_t)(b * C + ch)) * HW + R0 * IMG_W + X0;
            *(float4*)ob = ev;
            *(float4*)(ob + HW) = od;
        }
    }
}

// ---------------------------------------------------------------------------
extern "C" void kernel_launch(void* const* d_in, const int* in_sizes, int n_in,
                              void* d_out, int out_size) {
    const float* x   = (const float*)d_in[0];
    const float* wr  = (const float*)d_in[1];
    const float* br  = (const float*)d_in[2];
    const float* wsp = (const float*)d_in[3];
    const float* bs  = (const float*)d_in[4];
    float* out = (float*)d_out;

    static int once = 0;
    if (!once) {
        cudaFuncSetAttribute(k_gemm, cudaFuncAttributeMaxDynamicSharedMemorySize, SM_TOTAL);
        once = 1;
    }
    k_gemm<<<BB * (HW / 128), 256, SM_TOTAL>>>(x, wr, br, wsp, bs);
    dim3 g3(8, G, BB);
    k_invol<<<g3, 256>>>(x, out);
}

// round 13
// speedup vs baseline: 1.4331x; 1.1925x over previous
#include <cuda_runtime.h>
#include <cuda_fp16.h>
#include <cstdint>

#define BB 8
#define C 256
#define G 16
#define KK 9
#define GKK 144
#define HW 4096
#define IMG_W 64
#define IMG_H 64

typedef unsigned long long u64;
typedef unsigned int u32;

__device__ __align__(16) float g_kmap[BB * GKK * HW];

// ---------- scalar helpers ----------
__device__ __forceinline__ u64 ffma2(u64 a, u64 b, u64 c) {
    u64 d; asm("fma.rn.f32x2 %0, %1, %2, %3;" : "=l"(d) : "l"(a), "l"(b), "l"(c)); return d;
}
__device__ __forceinline__ u64 pk(float lo, float hi) {
    u64 r; asm("mov.b64 %0, {%1, %2};" : "=l"(r) : "f"(lo), "f"(hi)); return r;
}
__device__ __forceinline__ float lo32(u64 v) { return __uint_as_float((u32)v); }
__device__ __forceinline__ float hi32(u64 v) { return __uint_as_float((u32)(v >> 32)); }

// fp16 split: hi = fp16(v), lo = fp16(v - hi)
__device__ __forceinline__ u32 h2u(__half2 h) { u32 r; memcpy(&r, &h, 4); return r; }
__device__ __forceinline__ void split2h(float v0, float v1, u32& h2, u32& l2) {
    __half2 h = __floats2half2_rn(v0, v1);
    h2 = h2u(h);
    l2 = h2u(__floats2half2_rn(v0 - __low2float(h), v1 - __high2float(h)));
}
__device__ __forceinline__ void cvt4h(float4 v, u64& h, u64& l) {
    u32 h0, l0, h1, l1;
    split2h(v.x, v.y, h0, l0);
    split2h(v.z, v.w, h1, l1);
    h = (u64)h0 | ((u64)h1 << 32);
    l = (u64)l0 | ((u64)l1 << 32);
}
__device__ __forceinline__ u64 cvt4h1(float4 v) {
    u32 a = h2u(__floats2half2_rn(v.x, v.y));
    u32 b = h2u(__floats2half2_rn(v.z, v.w));
    return (u64)a | ((u64)b << 32);
}
__device__ __forceinline__ u32 smem_u32(const void* p) {
    u32 a; asm("{ .reg .u64 t; cvta.to.shared.u64 t, %1; cvt.u32.u64 %0, t; }" : "=r"(a) : "l"(p));
    return a;
}

#define MMA(d, a, b0, b1) \
    asm volatile("mma.sync.aligned.m16n8k16.row.col.f32.f16.f16.f32 " \
        "{%0,%1,%2,%3}, {%4,%5,%6,%7}, {%8,%9}, {%0,%1,%2,%3};" \
        : "+f"((d)[0]), "+f"((d)[1]), "+f"((d)[2]), "+f"((d)[3]) \
        : "r"((a)[0]), "r"((a)[1]), "r"((a)[2]), "r"((a)[3]), "r"(b0), "r"(b1))

#define LDSM4T(r, addr) \
    asm volatile("ldmatrix.sync.aligned.m8n8.x4.trans.shared.b16 {%0,%1,%2,%3}, [%4];" \
        : "=r"((r)[0]), "=r"((r)[1]), "=r"((r)[2]), "=r"((r)[3]) : "r"(addr))

#define LDSM4(r, addr) \
    asm volatile("ldmatrix.sync.aligned.m8n8.x4.shared.b16 {%0,%1,%2,%3}, [%4];" \
        : "=r"((r)[0]), "=r"((r)[1]), "=r"((r)[2]), "=r"((r)[3]) : "r"(addr))

// smem byte layout (k_gemm)
#define OFF_XH   0
#define OFF_XL   16384
#define OFF_W1H  32768
#define OFF_WSPH 43008
#define SM_TOTAL 63744

// ---------------------------------------------------------------------------
// k_gemm: unchanged from R12 (fp16 2-product HMMA, ~18us).
// ---------------------------------------------------------------------------
__global__ __launch_bounds__(256, 2)
void k_gemm(const float* __restrict__ x, const float* __restrict__ wr,
            const float* __restrict__ br, const float* __restrict__ wsp,
            const float* __restrict__ bs) {
    extern __shared__ __align__(16) char smem[];
    const int tid = threadIdx.x, wid = tid >> 5, lane = tid & 31;
    const int b = blockIdx.x >> 5, pt = (blockIdx.x & 31) << 7;
    const u32 sbase = smem_u32(smem);

#pragma unroll
    for (int i = 0; i < 9; i++) {
        int f4 = tid + i * 256;
        float4 v = *(const float4*)(wsp + f4 * 4);
        int n = f4 >> 4, kc = (f4 & 15) * 4;
        *(u64*)(smem + OFF_WSPH + n * 144 + kc * 2) = cvt4h1(v);
    }
    {
        const int c = tid >> 3, pxb = (tid & 7) * 16;
        const float* xsrc = x + ((size_t)(b * C + c)) * HW + pt + pxb;
        const int csw = (c & 7) << 3;
#pragma unroll
        for (int q = 0; q < 4; q++) {
            float4 v = *(const float4*)(xsrc + q * 4);
            int col = (pxb + q * 4) ^ csw;
            u64 h, l;
            cvt4h(v, h, l);
            *(u64*)(smem + OFF_XH + c * 256 + col * 2) = h;
            *(u64*)(smem + OFF_XL + c * 256 + col * 2) = l;
        }
        const int n = tid >> 2, koff = (tid & 3) * 8;
#pragma unroll
        for (int q = 0; q < 2; q++) {
            float4 v = *(const float4*)(wr + n * C + koff + q * 4);
            *(u64*)(smem + OFF_W1H + n * 80 + (koff + q * 4) * 2) = cvt4h1(v);
        }
    }
    __syncthreads();

    float acc1[8][4];
#pragma unroll
    for (int j = 0; j < 8; j++)
#pragma unroll
        for (int q = 0; q < 4; q++) acc1[j][q] = 0.f;

    const int m0 = wid * 16;
    const int grp = lane >> 3, li = lane & 7;
    const int krow_off = ((grp & 2) << 2) + li;
    const int coladd = (grp & 1) << 3;
    const int brow = ((lane >> 4) << 3) + li;
    const int bkadd = (grp & 1) << 3;

#pragma unroll 1
    for (int ck = 0; ck < 8; ck++) {
        const int cur = ck & 1, nxt = cur ^ 1;
        float4 xr[4], wrr[2];
        if (ck < 7) {
            const int c = tid >> 3, pxb = (tid & 7) * 16;
            const float* xsrc = x + ((size_t)(b * C + (ck + 1) * 32 + c)) * HW + pt + pxb;
#pragma unroll
            for (int q = 0; q < 4; q++) xr[q] = *(const float4*)(xsrc + q * 4);
            const int n = tid >> 2, koff = (tid & 3) * 8;
#pragma unroll
            for (int q = 0; q < 2; q++)
                wrr[q] = *(const float4*)(wr + n * C + (ck + 1) * 32 + koff + q * 4);
        }
        const u32 sxh = sbase + OFF_XH + cur * 8192;
        const u32 sw1h = sbase + OFF_W1H + cur * 5120;

#pragma unroll
        for (int ks = 0; ks < 2; ks++) {
            const int kb = ks * 16;
            u32 AH[4], AL[4];
            {
                int col = (m0 + coladd) ^ (li << 3);
                u32 ah = sxh + (u32)((kb + krow_off) * 256 + col * 2);
                LDSM4T(AH, ah);
                LDSM4T(AL, ah + 16384);
            }
#pragma unroll
            for (int nj2 = 0; nj2 < 4; nj2++) {
                u32 boff = (u32)((nj2 * 16 + brow) * 80 + (kb + bkadd) * 2);
                u32 BH[4];
                LDSM4(BH, sw1h + boff);
                MMA(acc1[2 * nj2], AH, BH[0], BH[1]);
                MMA(acc1[2 * nj2], AL, BH[0], BH[1]);
                MMA(acc1[2 * nj2 + 1], AH, BH[2], BH[3]);
                MMA(acc1[2 * nj2 + 1], AL, BH[2], BH[3]);
            }
        }
        if (ck < 7) {
            const int c = tid >> 3, pxb = (tid & 7) * 16;
            const int csw = (c & 7) << 3;
#pragma unroll
            for (int q = 0; q < 4; q++) {
                int col = (pxb + q * 4) ^ csw;
                u64 h, l;
                cvt4h(xr[q], h, l);
                *(u64*)(smem + OFF_XH + nxt * 8192 + c * 256 + col * 2) = h;
                *(u64*)(smem + OFF_XL + nxt * 8192 + c * 256 + col * 2) = l;
            }
            const int n = tid >> 2, koff = (tid & 3) * 8;
#pragma unroll
            for (int q = 0; q < 2; q++)
                *(u64*)(smem + OFF_W1H + nxt * 5120 + n * 80 + (koff + q * 4) * 2) = cvt4h1(wrr[q]);
        }
        __syncthreads();
    }

    u32 A2H[4][4], A2L[4][4];
#pragma unroll
    for (int ks = 0; ks < 4; ks++) {
        int o0 = ks * 16 + (lane & 3) * 2;
        float b0 = __ldg(br + o0),     b1 = __ldg(br + o0 + 1);
        float b8 = __ldg(br + o0 + 8), b9 = __ldg(br + o0 + 9);
        const float* t0 = acc1[2 * ks];
        const float* t1 = acc1[2 * ks + 1];
        float v0 = fmaxf(t0[0] + b0, 0.f), v1 = fmaxf(t0[1] + b1, 0.f);
        float v2 = fmaxf(t0[2] + b0, 0.f), v3 = fmaxf(t0[3] + b1, 0.f);
        float w0 = fmaxf(t1[0] + b8, 0.f), w1 = fmaxf(t1[1] + b9, 0.f);
        float w2 = fmaxf(t1[2] + b8, 0.f), w3 = fmaxf(t1[3] + b9, 0.f);
        split2h(v0, v1, A2H[ks][0], A2L[ks][0]);
        split2h(v2, v3, A2H[ks][1], A2L[ks][1]);
        split2h(w0, w1, A2H[ks][2], A2L[ks][2]);
        split2h(w2, w3, A2H[ks][3], A2L[ks][3]);
    }

    const u32 swsph = sbase + OFF_WSPH;
    const int pxl = wid * 16 + (lane >> 2);
    float* kout = g_kmap + (size_t)(b * GKK) * HW + pt;
#pragma unroll 1
    for (int nj2 = 0; nj2 < 9; nj2++) {
        float a2e[4] = {0.f, 0.f, 0.f, 0.f};
        float a2o[4] = {0.f, 0.f, 0.f, 0.f};
#pragma unroll
        for (int ks = 0; ks < 4; ks++) {
            u32 boff = (u32)((nj2 * 16 + brow) * 144 + (ks * 16 + bkadd) * 2);
            u32 BH[4];
            LDSM4(BH, swsph + boff);
            MMA(a2e, A2H[ks], BH[0], BH[1]);
            MMA(a2e, A2L[ks], BH[0], BH[1]);
            MMA(a2o, A2H[ks], BH[2], BH[3]);
            MMA(a2o, A2L[ks], BH[2], BH[3]);
        }
#pragma unroll
        for (int half = 0; half < 2; half++) {
            const float* a2 = half ? a2o : a2e;
            int o0 = (nj2 * 2 + half) * 8 + (lane & 3) * 2;
            float c0 = __ldg(bs + o0), c1 = __ldg(bs + o0 + 1);
            kout[(size_t)o0 * HW + pxl]           = a2[0] + c0;
            kout[(size_t)(o0 + 1) * HW + pxl]     = a2[1] + c1;
            kout[(size_t)o0 * HW + pxl + 8]       = a2[2] + c0;
            kout[(size_t)(o0 + 1) * HW + pxl + 8] = a2[3] + c1;
        }
    }
}

// ---------------------------------------------------------------------------
// k_invol v2: planar per-channel smem planes (64-float rows, zero padding
// columns), boundary columns via width-16 warp shuffles. Conflict-free
// LDS.128/STS.128 everywhere. Same fp32 arithmetic as before.
// CTA = (strip of 8 rows, g, b); 256 thr = cph(2) x rr(8) x t4(16).
// Each thread: 8 channels x 4 cols x 1 row = 32 outputs.
// ---------------------------------------------------------------------------
__global__ __launch_bounds__(256, 4) void k_invol(const float* __restrict__ x,
                                                  float* __restrict__ out) {
    __shared__ __align__(16) float sm[16 * 10 * 64];   // 40 KB planar
    const int tid = threadIdx.x, strip = blockIdx.x, g = blockIdx.y, b = blockIdx.z;
    const int chbase = g * 16;
    const int cph = tid >> 7;          // 0..1 -> channels cph*8 .. cph*8+7
    const int rr  = (tid >> 4) & 7;    // output row within strip
    const int t4  = tid & 15;          // col group (4 cols)
    const int R0  = strip * 8 + rr, X0 = t4 * 4;

    // --- kmap loads first (in flight across halo load + barrier) ---
    const float* kbase = g_kmap + ((size_t)(b * G + g)) * KK * HW + R0 * IMG_W + X0;
    float4 km[9];
#pragma unroll
    for (int k = 0; k < 9; k++) km[k] = *(const float4*)(kbase + (size_t)k * HW);

    // --- halo load: 16 ch x 10 rows x 64 cols, planar, fully coalesced ---
#pragma unroll
    for (int it = 0; it < 10; it++) {
        int lin = tid + it * 256;
        int ch = lin / 160;
        int rem = lin - ch * 160;
        int r = rem >> 4, c4 = rem & 15;
        int R = strip * 8 + r - 1;
        float4 v = make_float4(0.f, 0.f, 0.f, 0.f);
        if ((unsigned)R < (unsigned)IMG_H)
            v = *(const float4*)(x + ((size_t)(b * C + chbase + ch)) * HW + R * IMG_W + c4 * 4);
        *(float4*)&sm[ch * 640 + r * 64 + c4 * 4] = v;
    }

    // kmap column pairs (built while loads land; reused across all channels)
    u64 kxy[9], kzw[9];
#pragma unroll
    for (int k = 0; k < 9; k++) {
        kxy[k] = pk(km[k].x, km[k].y);
        kzw[k] = pk(km[k].z, km[k].w);
    }
    __syncthreads();

#pragma unroll
    for (int ci = 0; ci < 8; ci++) {
        const int ch = cph * 8 + ci;
        const float* pl = &sm[ch * 640 + rr * 64 + X0];
        u64 acc0 = 0ull, acc1 = 0ull;
#pragma unroll
        for (int dy = 0; dy < 3; dy++) {
            ulonglong2 q = *(const ulonglong2*)(pl + dy * 64);
            float a0 = lo32(q.x), a1 = hi32(q.x), a2 = lo32(q.y), a3 = hi32(q.y);
            float s  = __shfl_up_sync(0xFFFFFFFFu, a3, 1, 16);    // x(X0-1)
            float b0 = __shfl_down_sync(0xFFFFFFFFu, a0, 1, 16);  // x(X0+4)
            if (t4 == 0)  s  = 0.f;   // image left pad
            if (t4 == 15) b0 = 0.f;   // image right pad
            u64 pm  = pk(s,  a0);
            u64 p12 = pk(a1, a2);
            u64 p34 = pk(a3, b0);
            acc0 = ffma2(pm,  kxy[dy * 3 + 0], acc0);
            acc0 = ffma2(q.x, kxy[dy * 3 + 1], acc0);
            acc0 = ffma2(p12, kxy[dy * 3 + 2], acc0);
            acc1 = ffma2(p12, kzw[dy * 3 + 0], acc1);
            acc1 = ffma2(q.y, kzw[dy * 3 + 1], acc1);
            acc1 = ffma2(p34, kzw[dy * 3 + 2], acc1);
        }
        float4 r4;
        r4.x = lo32(acc0); r4.y = hi32(acc0);
        r4.z = lo32(acc1); r4.w = hi32(acc1);
        *(float4*)(out + ((size_t)(b * C + chbase + ch)) * HW + R0 * IMG_W + X0) = r4;
    }
}

// ---------------------------------------------------------------------------
extern "C" void kernel_launch(void* const* d_in, const int* in_sizes, int n_in,
                              void* d_out, int out_size) {
    const float* x   = (const float*)d_in[0];
    const float* wr  = (const float*)d_in[1];
    const float* br  = (const float*)d_in[2];
    const float* wsp = (const float*)d_in[3];
    const float* bs  = (const float*)d_in[4];
    float* out = (float*)d_out;

    static int once = 0;
    if (!once) {
        cudaFuncSetAttribute(k_gemm, cudaFuncAttributeMaxDynamicSharedMemorySize, SM_TOTAL);
        once = 1;
    }
    k_gemm<<<BB * (HW / 128), 256, SM_TOTAL>>>(x, wr, br, wsp, bs);
    dim3 g3(8, G, BB);
    k_invol<<<g3, 256>>>(x, out);
}